// round 10
// baseline (speedup 1.0000x reference)
#include <cuda_runtime.h>
#include <cuda_bf16.h>
#include <cstdint>

#define NB 4
typedef unsigned long long ull;
typedef unsigned int u32;

// ---------------- scratch ----------------
__device__ float g_om[NB * 27 * 64 * 64];
__device__ float g_y[NB * 128 * 64 * 64];
__device__ float g_up[NB * 128 * 128 * 128];
__device__ float g_woffT[2304 * 32];
__device__ __nv_bfloat16 g_wAH[36 * 8192];     // mdcn weights hi [chunk][oc][kin]
__device__ __nv_bfloat16 g_wAL[36 * 8192];     // mdcn weights lo
__device__ __nv_bfloat16 g_wuH[4 * 8 * 8192];  // deconv weights hi [parity][chunk][oc][kin]
__device__ __nv_bfloat16 g_wuL[4 * 8 * 8192];
__device__ float g_bn1s[128], g_bn1t[128];
__device__ float g_bn2s[128], g_bn2t[128];

// ---------------- helpers ----------------
__device__ __forceinline__ ull dup2(float v) {
    ull r; asm("mov.b64 %0, {%1,%1};" : "=l"(r) : "f"(v)); return r;
}
__device__ __forceinline__ void fma2(ull& d, ull a, ull b) {
    asm("fma.rn.f32x2 %0, %1, %2, %0;" : "+l"(d) : "l"(a), "l"(b));
}
__device__ __forceinline__ float2 unpk(ull v) {
    float2 r; asm("mov.b64 {%0, %1}, %2;" : "=f"(r.x), "=f"(r.y) : "l"(v)); return r;
}
__device__ __forceinline__ void cp16(void* s, const void* g) {
    unsigned sa = (unsigned)__cvta_generic_to_shared(s);
    asm volatile("cp.async.ca.shared.global [%0], [%1], 16;" :: "r"(sa), "l"(g));
}
__device__ __forceinline__ void cp_commit() { asm volatile("cp.async.commit_group;"); }
__device__ __forceinline__ void cp_wait0()  { asm volatile("cp.async.wait_group 0;" ::: "memory"); }

__device__ __forceinline__ u32 smem_u32(const void* p) {
    u32 a; asm("{ .reg .u64 t; cvta.to.shared.u64 t, %1; cvt.u32.u64 %0, t; }" : "=r"(a) : "l"(p));
    return a;
}
__device__ __forceinline__ void ldsm4(u32* r, u32 addr) {
    asm volatile("ldmatrix.sync.aligned.m8n8.x4.shared.b16 {%0,%1,%2,%3}, [%4];"
                 : "=r"(r[0]), "=r"(r[1]), "=r"(r[2]), "=r"(r[3]) : "r"(addr));
}
__device__ __forceinline__ void mma16816(float* c, const u32* a, u32 b0, u32 b1) {
    asm volatile(
        "mma.sync.aligned.m16n8k16.row.col.f32.bf16.bf16.f32 "
        "{%0,%1,%2,%3}, {%4,%5,%6,%7}, {%8,%9}, {%0,%1,%2,%3};"
        : "+f"(c[0]), "+f"(c[1]), "+f"(c[2]), "+f"(c[3])
        : "r"(a[0]), "r"(a[1]), "r"(a[2]), "r"(a[3]), "r"(b0), "r"(b1));
}
#define BAR_SYNC(id)   asm volatile("bar.sync %0, 256;"   :: "r"(id) : "memory")
#define BAR_ARRIVE(id) asm volatile("bar.arrive %0, 256;" :: "r"(id) : "memory")

// row pitch for MMA tiles: 72 bf16 = 144 bytes (16B-aligned, conflict-free ldmatrix)
#define PITCH 72
#define PITCHB 144

// ---------------- kernel 0: weight re-layouts + bf16 hi/lo splits ----------------
__global__ void __launch_bounds__(256) prep_weights(const float* __restrict__ w_off,
                                                    const float* __restrict__ w_dcn,
                                                    const float* __restrict__ w_up) {
    int idx = blockIdx.x * 256 + threadIdx.x;
    const int NW1 = 36 * 8192;
    const int NW2 = 4 * 8 * 8192;
    if (idx < NW1) {
        int chunk = idx >> 13;
        int r = idx & 8191;
        int oc = r >> 6, kin = r & 63;
        int k = chunk * 64 + kin;
        float v = w_dcn[oc * 2304 + k];
        __nv_bfloat16 hi = __float2bfloat16(v);
        __nv_bfloat16 lo = __float2bfloat16(v - __bfloat162float(hi));
        g_wAH[idx] = hi;
        g_wAL[idx] = lo;
        return;
    }
    int i2 = idx - NW1;
    if (i2 < NW2) {
        int p = i2 >> 16;
        int r2 = i2 & 65535;
        int chunk = r2 >> 13;
        int r = r2 & 8191;
        int oc = r >> 6, kin = r & 63;
        int k = chunk * 64 + kin;
        int c = k >> 2, tap = k & 3;
        int ty = tap >> 1, tx = tap & 1;
        int pY = p >> 1, pX = p & 1;
        int ky = (pY ^ 1) + 2 * ty;
        int kx = (pX ^ 1) + 2 * tx;
        float v = w_up[((c * 128 + oc) * 4 + ky) * 4 + kx];
        __nv_bfloat16 hi = __float2bfloat16(v);
        __nv_bfloat16 lo = __float2bfloat16(v - __bfloat162float(hi));
        g_wuH[i2] = hi;
        g_wuL[i2] = lo;
        return;
    }
    int i3 = i2 - NW2;
    if (i3 < 2304 * 32) {
        int ck = i3 >> 5, oc = i3 & 31;
        g_woffT[i3] = (oc < 27) ? w_off[oc * 2304 + ck] : 0.f;
    }
}

// ---------------- dummy (launch-slot padding so ncu -s5 captures mdcn) ----------------
__global__ void dummy_kernel() {}

// ---------------- kernel 1: 3x3 offset conv (SIMT fma2) ------------
__global__ void __launch_bounds__(256, 2) conv_off_kernel(const float* __restrict__ x,
                                                          const float* __restrict__ b_off) {
    __shared__ float As[2][36][32];
    __shared__ float Bs[2][36][64];
    int b = blockIdx.x >> 6;
    int h = blockIdx.x & 63;
    int t = threadIdx.x;
    int ocp = t >> 4;
    int pb = (t & 15) << 2;
    const float* xb = x + b * 256 * 4096;
    ull acc[4];
#pragma unroll
    for (int j = 0; j < 4; j++) acc[j] = 0ull;
    float xv[9];

#define COFF_LOADB(c0)                                                          \
    {                                                                           \
        _Pragma("unroll")                                                       \
        for (int i = 0; i < 9; i++) {                                           \
            int e = t + (i << 8);                                               \
            int kc = e >> 6, wx = e & 63;                                       \
            int ci = kc / 9, kk = kc - ci * 9;                                  \
            int ky = kk / 3, kx = kk - ky * 3;                                  \
            int yy = h + ky - 1, xx = wx + kx - 1;                              \
            float v = 0.f;                                                      \
            if ((unsigned)yy < 64u && (unsigned)xx < 64u)                       \
                v = xb[((c0) + ci) * 4096 + yy * 64 + xx];                      \
            xv[i] = v;                                                          \
        }                                                                       \
    }
#define COFF_STOREB(dst)                                                        \
    {                                                                           \
        _Pragma("unroll")                                                       \
        for (int i = 0; i < 9; i++) {                                           \
            int e = t + (i << 8);                                               \
            int kc = e >> 6, wx = e & 63;                                       \
            Bs[dst][kc][wx] = xv[i];                                            \
        }                                                                       \
    }
#define COFF_LOADA(c0, dst)                                                     \
    {                                                                           \
        const float4* wsrc = (const float4*)(g_woffT + (c0) * 9 * 32);          \
        _Pragma("unroll")                                                       \
        for (int i = 0; i < 2; i++) {                                           \
            int e = t + (i << 8);                                               \
            if (e < 288) cp16(&((float4*)As[dst])[e], wsrc + e);                \
        }                                                                       \
        cp_commit();                                                            \
    }
#define COFF_COMPUTE(cc)                                                        \
    {                                                                           \
        _Pragma("unroll")                                                       \
        for (int kc = 0; kc < 36; kc++) {                                       \
            ull Au = *(const ull*)&As[cc][kc][ocp * 2];                         \
            float4 bv = *(const float4*)&Bs[cc][kc][pb];                        \
            fma2(acc[0], Au, dup2(bv.x));                                       \
            fma2(acc[1], Au, dup2(bv.y));                                       \
            fma2(acc[2], Au, dup2(bv.z));                                       \
            fma2(acc[3], Au, dup2(bv.w));                                       \
        }                                                                       \
    }

    int cur = 0;
    COFF_LOADA(0, 0)
    COFF_LOADB(0)
    COFF_STOREB(0)
    cp_wait0();
    __syncthreads();
    for (int c0 = 4; c0 < 256; c0 += 4) {
        int nxt = cur ^ 1;
        COFF_LOADA(c0, nxt)
        COFF_LOADB(c0)
        COFF_COMPUTE(cur)
        COFF_STOREB(nxt)
        cp_wait0();
        __syncthreads();
        cur = nxt;
    }
    COFF_COMPUTE(cur)

    int oc = 2 * ocp;
    if (oc < 27) {
        float2 p0 = unpk(acc[0]), p1 = unpk(acc[1]), p2 = unpk(acc[2]), p3 = unpk(acc[3]);
        float bo = b_off[oc];
        float4 lo = make_float4(p0.x + bo, p1.x + bo, p2.x + bo, p3.x + bo);
        *(float4*)&g_om[((b * 27 + oc) * 64 + h) * 64 + pb] = lo;
        if (oc + 1 < 27) {
            float b1 = b_off[oc + 1];
            float4 hi = make_float4(p0.y + b1, p1.y + b1, p2.y + b1, p3.y + b1);
            *(float4*)&g_om[((b * 27 + oc + 1) * 64 + h) * 64 + pb] = hi;
        }
    }
}

// ======== shared warp-specialized MMA consumer macro (M32 stripe x N64 per warp) ========
// uses: sb, aoffBase, bbase, acc[2][8][4]
#define MMA_WS(cc, AH, AL, BH, BL)                                              \
    {                                                                           \
        u32 aH = sb + AH[cc], aL = sb + AL[cc];                                 \
        u32 bH = sb + BH[cc], bL = sb + BL[cc];                                 \
        _Pragma("unroll")                                                       \
        for (int ks = 0; ks < 4; ks++) {                                        \
            u32 ka = (u32)ks * 32;                                              \
            u32 ah0[4], ah1[4], al0[4], al1[4];                                 \
            ldsm4(ah0, aH + aoffBase + ka);                                     \
            ldsm4(ah1, aH + aoffBase + ka + 16 * PITCHB);                       \
            ldsm4(al0, aL + aoffBase + ka);                                     \
            ldsm4(al1, aL + aoffBase + ka + 16 * PITCHB);                       \
            u32 bh[4][4], bl[4][4];                                             \
            _Pragma("unroll")                                                   \
            for (int g = 0; g < 4; g++) {                                       \
                ldsm4(bh[g], bH + bbase + (u32)g * 16 * PITCHB + ka);           \
                ldsm4(bl[g], bL + bbase + (u32)g * 16 * PITCHB + ka);           \
            }                                                                   \
            _Pragma("unroll")                                                   \
            for (int g = 0; g < 4; g++) {                                       \
                mma16816(acc[0][2 * g],     ah0, bh[g][0], bh[g][1]);           \
                mma16816(acc[0][2 * g + 1], ah0, bh[g][2], bh[g][3]);           \
                mma16816(acc[1][2 * g],     ah1, bh[g][0], bh[g][1]);           \
                mma16816(acc[1][2 * g + 1], ah1, bh[g][2], bh[g][3]);           \
                mma16816(acc[0][2 * g],     ah0, bl[g][0], bl[g][1]);           \
                mma16816(acc[0][2 * g + 1], ah0, bl[g][2], bl[g][3]);           \
                mma16816(acc[1][2 * g],     ah1, bl[g][0], bl[g][1]);           \
                mma16816(acc[1][2 * g + 1], ah1, bl[g][2], bl[g][3]);           \
                mma16816(acc[0][2 * g],     al0, bh[g][0], bh[g][1]);           \
                mma16816(acc[0][2 * g + 1], al0, bh[g][2], bh[g][3]);           \
                mma16816(acc[1][2 * g],     al1, bh[g][0], bh[g][1]);           \
                mma16816(acc[1][2 * g + 1], al1, bh[g][2], bh[g][3]);           \
            }                                                                   \
        }                                                                       \
    }

// ================= mdcn: warp-specialized (4 producer + 4 MMA warps) =================
#define MD_MW   0                   // metaW: 576 * 16 = 9216
#define MD_MI   9216                // metaI: 576 * 4 = 2304
#define MD_AH0  11520               // A tiles: 128 x 72 bf16 = 18432 each
#define MD_AH1  29952
#define MD_AL0  48384
#define MD_AL1  66816
#define MD_BH0  85248               // B tiles: 64 x 72 bf16 = 9216 each
#define MD_BH1  94464
#define MD_BL0  103680
#define MD_BL1  112896
#define MD_DS   MD_AH0              // epilogue 128 x 68 f32 = 34816
#define MD_SMEM 122112

__global__ void __launch_bounds__(256)
mdcn_mma_kernel(const float* __restrict__ x, const float* __restrict__ b_dcn) {
    extern __shared__ char sm[];
    u32 sb = smem_u32(sm);
    int b = blockIdx.x >> 6;
    int h = blockIdx.x & 63;
    int t = threadIdx.x;
    int wid = t >> 5;
    int lane = t & 31;

    float4* metaW = (float4*)(sm + MD_MW);
    u32* metaI = (u32*)(sm + MD_MI);

    // bilinear meta for 64 pixels x 9 taps (all 256 threads)
    for (int e = t; e < 576; e += 256) {
        int pixl = e / 9;
        int k = e - pixl * 9;
        int w = pixl;
        const float* omb = g_om + (b * 27) * 4096 + h * 64 + w;
        float dy = omb[(2 * k) * 4096];
        float dx = omb[(2 * k + 1) * 4096];
        float mr = omb[(18 + k) * 4096];
        float m = 1.f / (1.f + expf(-mr));
        int ky = k / 3, kx = k - ky * 3;
        float ys = (float)(h - 1 + ky) + dy;
        float xs = (float)(w - 1 + kx) + dx;
        float y0f = floorf(ys), x0f = floorf(xs);
        float ly = ys - y0f, lx = xs - x0f;
        int y0 = (int)y0f, x0 = (int)x0f;
        int y1 = y0 + 1, x1 = x0 + 1;
        float vy0 = ((unsigned)y0 < 64u) ? 1.f : 0.f;
        float vy1 = ((unsigned)y1 < 64u) ? 1.f : 0.f;
        float vx0 = ((unsigned)x0 < 64u) ? 1.f : 0.f;
        float vx1 = ((unsigned)x1 < 64u) ? 1.f : 0.f;
        int iy0 = min(max(y0, 0), 63), iy1 = min(max(y1, 0), 63);
        int ix0 = min(max(x0, 0), 63), ix1 = min(max(x1, 0), 63);
        float4 wv;
        wv.x = (1.f - ly) * (1.f - lx) * m * vy0 * vx0;
        wv.y = (1.f - ly) * lx * m * vy0 * vx1;
        wv.z = ly * (1.f - lx) * m * vy1 * vx0;
        wv.w = ly * lx * m * vy1 * vx1;
        metaW[e] = wv;
        metaI[e] = (u32)iy0 | ((u32)iy1 << 8) | ((u32)ix0 << 16) | ((u32)ix1 << 24);
    }
    __syncthreads();

    const int ahOff[2] = {MD_AH0, MD_AH1};
    const int alOff[2] = {MD_AL0, MD_AL1};
    const int bhOff[2] = {MD_BH0, MD_BH1};
    const int blOff[2] = {MD_BL0, MD_BL1};

    float acc[2][8][4];
    int m0 = wid * 32;

    if (wid < 4) {
        // ---------------- MMA warps ----------------
#pragma unroll
        for (int i = 0; i < 2; i++)
#pragma unroll
            for (int j = 0; j < 8; j++)
#pragma unroll
                for (int q = 0; q < 4; q++) acc[i][j][q] = 0.f;
        u32 aoffBase = (u32)(m0 + (lane & 15)) * PITCHB + ((lane >> 4) << 4);
        u32 bbase = (u32)((lane & 7) + ((lane >> 4) << 3)) * PITCHB + (((lane >> 3) & 1) << 4);
        for (int c = 0; c < 36; c++) {
            int buf = c & 1;
            BAR_SYNC(1 + buf);          // wait FULL
            MMA_WS(buf, ahOff, alOff, bhOff, blOff)
            BAR_ARRIVE(3 + buf);        // signal EMPTY
        }
    } else {
        // ---------------- producer warps ----------------
        int pt = t & 127;
        int px = pt & 63;
        int kin0 = pt >> 6;
        const float* xb = x + b * 256 * 4096;
        for (int c = 0; c < 36; c++) {
            int buf = c & 1;
            if (c >= 2) BAR_SYNC(3 + buf);   // wait EMPTY
            {
                const char* srcH = (const char*)g_wAH + c * 16384;
                const char* srcL = (const char*)g_wAL + c * 16384;
                char* dH = sm + ahOff[buf];
                char* dL = sm + alOff[buf];
#pragma unroll
                for (int i = 0; i < 8; i++) {
                    int e = pt + (i << 7);
                    int oc = e >> 3, s = e & 7;
                    cp16(dH + oc * PITCHB + s * 16, srcH + e * 16);
                    cp16(dL + oc * PITCHB + s * 16, srcL + e * 16);
                }
                cp_commit();
            }
            {
                char* bh = sm + bhOff[buf];
                char* bl = sm + blOff[buf];
#pragma unroll
                for (int i = 0; i < 32; i++) {
                    int kin = kin0 + 2 * i;
                    int k = c * 64 + kin;
                    int ci = k / 9;
                    int kk = k - 9 * ci;
                    int mi = px * 9 + kk;
                    u32 pk = metaI[mi];
                    float4 wv = metaW[mi];
                    const float* xc = xb + (ci << 12);
                    int iy0 = pk & 255, iy1 = (pk >> 8) & 255;
                    int ix0 = (pk >> 16) & 255, ix1 = pk >> 24;
                    float v = wv.x * xc[iy0 * 64 + ix0] + wv.y * xc[iy0 * 64 + ix1]
                            + wv.z * xc[iy1 * 64 + ix0] + wv.w * xc[iy1 * 64 + ix1];
                    __nv_bfloat16 hi = __float2bfloat16(v);
                    __nv_bfloat16 lo = __float2bfloat16(v - __bfloat162float(hi));
                    int off = (px * PITCH + kin) * 2;
                    *(__nv_bfloat16*)(bh + off) = hi;
                    *(__nv_bfloat16*)(bl + off) = lo;
                }
            }
            cp_wait0();
            BAR_ARRIVE(1 + buf);        // signal FULL
        }
    }
    __syncthreads();

    // epilogue: MMA warps dump acc -> smem; all threads write out coalesced
    float* Ds = (float*)(sm + MD_DS);
    if (wid < 4) {
#pragma unroll
        for (int mt = 0; mt < 2; mt++)
#pragma unroll
            for (int nt = 0; nt < 8; nt++) {
                int m = m0 + mt * 16 + (lane >> 2);
                int n = nt * 8 + ((lane & 3) << 1);
                float* cp = acc[mt][nt];
                *(float2*)&Ds[m * 68 + n] = make_float2(cp[0], cp[1]);
                *(float2*)&Ds[(m + 8) * 68 + n] = make_float2(cp[2], cp[3]);
            }
    }
    __syncthreads();
    {
        int oc8 = (t >> 4) * 8, w4 = (t & 15) * 4;
#pragma unroll
        for (int op = 0; op < 8; op++) {
            int oc = oc8 + op;
            float4 v = *(float4*)&Ds[oc * 68 + w4];
            float bb = b_dcn[oc];
            v.x += bb; v.y += bb; v.z += bb; v.w += bb;
            *(float4*)&g_y[((b * 128 + oc) << 12) + h * 64 + w4] = v;
        }
    }
}

// ---------------- BN stats ----------------
__global__ void __launch_bounds__(1024) bn_stats_kernel(const float* __restrict__ src, int shift,
                                                        const float* __restrict__ gamma,
                                                        const float* __restrict__ beta,
                                                        float* gs, float* gt) {
    int c = blockIdx.x;
    int t = threadIdx.x;
    float s = 0.f, q = 0.f;
    for (int i = t; i < (4 << (shift - 2)); i += 1024) {
        int bb = i >> (shift - 2);
        int r = i - (bb << (shift - 2));
        float4 v = ((const float4*)src)[(size_t)((bb * 128 + c) << (shift - 2)) + r];
        s += v.x + v.y + v.z + v.w;
        q += v.x * v.x + v.y * v.y + v.z * v.z + v.w * v.w;
    }
    __shared__ float rs[1024], rq[1024];
    rs[t] = s; rq[t] = q;
    __syncthreads();
    for (int o = 512; o > 0; o >>= 1) {
        if (t < o) { rs[t] += rs[t + o]; rq[t] += rq[t + o]; }
        __syncthreads();
    }
    if (t == 0) {
        float inv = 1.f / (float)(4 << shift);
        float mean = rs[0] * inv;
        float var = rq[0] * inv - mean * mean;
        float sc = gamma[c] * rsqrtf(var + 1e-5f);
        gs[c] = sc;
        gt[c] = beta[c] - mean * sc;
    }
}

// ================= deconv: warp-specialized (4 producer + 4 MMA warps) =================
#define DC_AH0  0
#define DC_AH1  18432
#define DC_AL0  36864
#define DC_AL1  55296
#define DC_BH0  73728
#define DC_BH1  82944
#define DC_BL0  92160
#define DC_BL1  101376
#define DC_BN   110592              // bn1 scale/shift cache: 2 x 128 floats
#define DC_DS   0
#define DC_SMEM 111616

__global__ void __launch_bounds__(256)
deconv_mma_kernel() {
    extern __shared__ char sm[];
    u32 sb = smem_u32(sm);
    int b = blockIdx.x >> 8;
    int rem = blockIdx.x & 255;
    int Y = rem >> 1;
    int pX = rem & 1;
    int p = ((Y & 1) << 1) | pX;
    int t = threadIdx.x;
    int wid = t >> 5;
    int lane = t & 31;

    float* bnS = (float*)(sm + DC_BN);
    float* bnT = (float*)(sm + DC_BN + 512);
    if (t < 128) { bnS[t] = g_bn1s[t]; bnT[t] = g_bn1t[t]; }
    __syncthreads();

    const int ahOff[2] = {DC_AH0, DC_AH1};
    const int alOff[2] = {DC_AL0, DC_AL1};
    const int bhOff[2] = {DC_BH0, DC_BH1};
    const int blOff[2] = {DC_BL0, DC_BL1};

    float acc[2][8][4];
    int m0 = wid * 32;

    if (wid < 4) {
#pragma unroll
        for (int i = 0; i < 2; i++)
#pragma unroll
            for (int j = 0; j < 8; j++)
#pragma unroll
                for (int q = 0; q < 4; q++) acc[i][j][q] = 0.f;
        u32 aoffBase = (u32)(m0 + (lane & 15)) * PITCHB + ((lane >> 4) << 4);
        u32 bbase = (u32)((lane & 7) + ((lane >> 4) << 3)) * PITCHB + (((lane >> 3) & 1) << 4);
        for (int c = 0; c < 8; c++) {
            int buf = c & 1;
            BAR_SYNC(1 + buf);
            MMA_WS(buf, ahOff, alOff, bhOff, blOff)
            BAR_ARRIVE(3 + buf);
        }
    } else {
        int pt = t & 127;
        int px = pt & 63;
        int kin0 = pt >> 6;
        const float* yb = g_y + b * 128 * 4096;
        for (int c = 0; c < 8; c++) {
            int buf = c & 1;
            if (c >= 2) BAR_SYNC(3 + buf);
            {
                const char* srcH = (const char*)g_wuH + (p * 8 + c) * 16384;
                const char* srcL = (const char*)g_wuL + (p * 8 + c) * 16384;
                char* dH = sm + ahOff[buf];
                char* dL = sm + alOff[buf];
#pragma unroll
                for (int i = 0; i < 8; i++) {
                    int e = pt + (i << 7);
                    int oc = e >> 3, s = e & 7;
                    cp16(dH + oc * PITCHB + s * 16, srcH + e * 16);
                    cp16(dL + oc * PITCHB + s * 16, srcL + e * 16);
                }
                cp_commit();
            }
            {
                char* bh = sm + bhOff[buf];
                char* bl = sm + blOff[buf];
#pragma unroll
                for (int i = 0; i < 32; i++) {
                    int kin = kin0 + 2 * i;
                    int k = c * 64 + kin;
                    int cc2 = k >> 2;
                    int tap = k & 3;
                    int ky = ((Y & 1) ^ 1) + 2 * (tap >> 1);
                    int hh = (Y + 1 - ky) >> 1;
                    int kx = (pX ^ 1) + 2 * (tap & 1);
                    int ww = px + ((pX + 1 - kx) >> 1);
                    float v = 0.f;
                    if ((unsigned)hh < 64u && (unsigned)ww < 64u) {
                        float yv = yb[(cc2 << 12) + hh * 64 + ww];
                        v = fmaxf(yv * bnS[cc2] + bnT[cc2], 0.f);
                    }
                    __nv_bfloat16 hi = __float2bfloat16(v);
                    __nv_bfloat16 lo = __float2bfloat16(v - __bfloat162float(hi));
                    int off = (px * PITCH + kin) * 2;
                    *(__nv_bfloat16*)(bh + off) = hi;
                    *(__nv_bfloat16*)(bl + off) = lo;
                }
            }
            cp_wait0();
            BAR_ARRIVE(1 + buf);
        }
    }
    __syncthreads();

    float* Ds = (float*)(sm + DC_DS);
    if (wid < 4) {
#pragma unroll
        for (int mt = 0; mt < 2; mt++)
#pragma unroll
            for (int nt = 0; nt < 8; nt++) {
                int m = m0 + mt * 16 + (lane >> 2);
                int n = nt * 8 + ((lane & 3) << 1);
                float* cp = acc[mt][nt];
                *(float2*)&Ds[m * 68 + n] = make_float2(cp[0], cp[1]);
                *(float2*)&Ds[(m + 8) * 68 + n] = make_float2(cp[2], cp[3]);
            }
    }
    __syncthreads();
    {
        int oc8 = (t >> 4) * 8, w4 = (t & 15) * 4;
#pragma unroll
        for (int op = 0; op < 8; op++) {
            int oc = oc8 + op;
            float4 v = *(float4*)&Ds[oc * 68 + w4];
            size_t base = (size_t)((b * 128 + oc) * 128 + Y) * 128 + pX * 64 + w4;
            *(float4*)&g_up[base] = v;
        }
    }
}

// ---------------- BN2 + ReLU + parity de-interleave ----------------
__global__ void __launch_bounds__(256) final_kernel(float* __restrict__ out) {
    __shared__ float s[8][128];
    int row0 = blockIdx.x * 8;
    int r = threadIdx.x >> 5;
    int q = threadIdx.x & 31;
    int grow = row0 + r;
    ((float4*)s[r])[q] = ((const float4*)g_up)[grow * 32 + q];
    __syncthreads();
    int bo = grow >> 7;
    int oc = bo & 127;
    float sc = g_bn2s[oc], sh = g_bn2t[oc];
    float v0 = s[r][q * 2];
    float v1 = s[r][64 + q * 2];
    float v2 = s[r][q * 2 + 1];
    float v3 = s[r][64 + q * 2 + 1];
    float4 o4 = make_float4(fmaxf(v0 * sc + sh, 0.f), fmaxf(v1 * sc + sh, 0.f),
                            fmaxf(v2 * sc + sh, 0.f), fmaxf(v3 * sc + sh, 0.f));
    *(float4*)&out[grow * 128 + q * 4] = o4;
}

// ---------------- launch ----------------
extern "C" void kernel_launch(void* const* d_in, const int* in_sizes, int n_in,
                              void* d_out, int out_size) {
    const float* x      = (const float*)d_in[0];
    const float* w_off  = (const float*)d_in[1];
    const float* b_off  = (const float*)d_in[2];
    const float* w_dcn  = (const float*)d_in[3];
    const float* b_dcn  = (const float*)d_in[4];
    const float* gamma1 = (const float*)d_in[5];
    const float* beta1  = (const float*)d_in[6];
    const float* w_up   = (const float*)d_in[7];
    const float* gamma2 = (const float*)d_in[8];
    const float* beta2  = (const float*)d_in[9];

    (void)cudaFuncSetAttribute(mdcn_mma_kernel, cudaFuncAttributeMaxDynamicSharedMemorySize, MD_SMEM);
    (void)cudaFuncSetAttribute(deconv_mma_kernel, cudaFuncAttributeMaxDynamicSharedMemorySize, DC_SMEM);

    float* yptr;  cudaGetSymbolAddress((void**)&yptr, g_y);
    float* uptr;  cudaGetSymbolAddress((void**)&uptr, g_up);
    float* b1s;   cudaGetSymbolAddress((void**)&b1s, g_bn1s);
    float* b1t;   cudaGetSymbolAddress((void**)&b1t, g_bn1t);
    float* b2s;   cudaGetSymbolAddress((void**)&b2s, g_bn2s);
    float* b2t;   cudaGetSymbolAddress((void**)&b2t, g_bn2t);

    int prepN = 36 * 8192 + 4 * 8 * 8192 + 2304 * 32;
    prep_weights<<<(prepN + 255) / 256, 256>>>(w_off, w_dcn, w_up);   // launch 0
    conv_off_kernel<<<NB * 64, 256>>>(x, b_off);                      // launch 1
    dummy_kernel<<<1, 32>>>();                                        // launch 2
    dummy_kernel<<<1, 32>>>();                                        // launch 3
    dummy_kernel<<<1, 32>>>();                                        // launch 4
    mdcn_mma_kernel<<<NB * 64, 256, MD_SMEM>>>(x, b_dcn);             // launch 5 (ncu slot)
    bn_stats_kernel<<<128, 1024>>>(yptr, 12, gamma1, beta1, b1s, b1t);
    deconv_mma_kernel<<<NB * 256, 256, DC_SMEM>>>();
    bn_stats_kernel<<<128, 1024>>>(uptr, 14, gamma2, beta2, b2s, b2t);
    final_kernel<<<(NB * 128 * 128 * 128) / 1024, 256>>>((float*)d_out);
}

// round 11
// speedup vs baseline: 1.7425x; 1.7425x over previous
#include <cuda_runtime.h>
#include <cuda_bf16.h>
#include <cstdint>

#define NB 4
typedef unsigned long long ull;
typedef unsigned int u32;

// ---------------- scratch ----------------
__device__ float g_om[NB * 27 * 64 * 64];
__device__ float g_y[NB * 128 * 64 * 64];
__device__ float g_up[NB * 128 * 128 * 128];
__device__ float g_woffT[2304 * 32];
__device__ __nv_bfloat16 g_wAH[72 * 4096];     // mdcn weights hi [chunk32][oc][kin32]
__device__ __nv_bfloat16 g_wAL[72 * 4096];
__device__ __nv_bfloat16 g_wuH[4 * 16 * 4096]; // deconv weights hi [parity][chunk32][oc][kin32]
__device__ __nv_bfloat16 g_wuL[4 * 16 * 4096];
__device__ float g_bn1s[128], g_bn1t[128];
__device__ float g_bn2s[128], g_bn2t[128];

// ---------------- helpers ----------------
__device__ __forceinline__ ull dup2(float v) {
    ull r; asm("mov.b64 %0, {%1,%1};" : "=l"(r) : "f"(v)); return r;
}
__device__ __forceinline__ void fma2(ull& d, ull a, ull b) {
    asm("fma.rn.f32x2 %0, %1, %2, %0;" : "+l"(d) : "l"(a), "l"(b));
}
__device__ __forceinline__ float2 unpk(ull v) {
    float2 r; asm("mov.b64 {%0, %1}, %2;" : "=f"(r.x), "=f"(r.y) : "l"(v)); return r;
}
__device__ __forceinline__ void cp16(void* s, const void* g) {
    unsigned sa = (unsigned)__cvta_generic_to_shared(s);
    asm volatile("cp.async.ca.shared.global [%0], [%1], 16;" :: "r"(sa), "l"(g));
}
__device__ __forceinline__ void cp_commit() { asm volatile("cp.async.commit_group;"); }
__device__ __forceinline__ void cp_wait0()  { asm volatile("cp.async.wait_group 0;" ::: "memory"); }

__device__ __forceinline__ u32 smem_u32(const void* p) {
    u32 a; asm("{ .reg .u64 t; cvta.to.shared.u64 t, %1; cvt.u32.u64 %0, t; }" : "=r"(a) : "l"(p));
    return a;
}
__device__ __forceinline__ void ldsm4(u32* r, u32 addr) {
    asm volatile("ldmatrix.sync.aligned.m8n8.x4.shared.b16 {%0,%1,%2,%3}, [%4];"
                 : "=r"(r[0]), "=r"(r[1]), "=r"(r[2]), "=r"(r[3]) : "r"(addr));
}
__device__ __forceinline__ void mma16816(float* c, const u32* a, u32 b0, u32 b1) {
    asm volatile(
        "mma.sync.aligned.m16n8k16.row.col.f32.bf16.bf16.f32 "
        "{%0,%1,%2,%3}, {%4,%5,%6,%7}, {%8,%9}, {%0,%1,%2,%3};"
        : "+f"(c[0]), "+f"(c[1]), "+f"(c[2]), "+f"(c[3])
        : "r"(a[0]), "r"(a[1]), "r"(a[2]), "r"(a[3]), "r"(b0), "r"(b1));
}
// packed lo-split: d = {bf16(l0) lower, bf16(l1) upper}
__device__ __forceinline__ u32 cvtpk(float l0, float l1) {
    u32 r; asm("cvt.rn.bf16x2.f32 %0, %1, %2;" : "=r"(r) : "f"(l1), "f"(l0)); return r;
}

// pitch for chunk-32 tiles: 40 bf16 = 80 bytes (odd multiple of 16B -> conflict-free ldmatrix)
#define PITCHB 80

// ---------------- kernel 0: weight re-layouts + bf16 hi/lo splits ----------------
__global__ void __launch_bounds__(256) prep_weights(const float* __restrict__ w_off,
                                                    const float* __restrict__ w_dcn,
                                                    const float* __restrict__ w_up) {
    int idx = blockIdx.x * 256 + threadIdx.x;
    const int NW1 = 72 * 4096;
    const int NW2 = 4 * 16 * 4096;
    if (idx < NW1) {
        int chunk = idx >> 12;
        int r = idx & 4095;
        int oc = r >> 5, kin = r & 31;
        int k = chunk * 32 + kin;
        float v = w_dcn[oc * 2304 + k];
        __nv_bfloat16 hi = __float2bfloat16(v);
        __nv_bfloat16 lo = __float2bfloat16(v - __bfloat162float(hi));
        g_wAH[idx] = hi;
        g_wAL[idx] = lo;
        return;
    }
    int i2 = idx - NW1;
    if (i2 < NW2) {
        int p = i2 >> 16;
        int r2 = i2 & 65535;
        int chunk = r2 >> 12;
        int r = r2 & 4095;
        int oc = r >> 5, kin = r & 31;
        int k = chunk * 32 + kin;
        int c = k >> 2, tap = k & 3;
        int ty = tap >> 1, tx = tap & 1;
        int pY = p >> 1, pX = p & 1;
        int ky = (pY ^ 1) + 2 * ty;
        int kx = (pX ^ 1) + 2 * tx;
        float v = w_up[((c * 128 + oc) * 4 + ky) * 4 + kx];
        __nv_bfloat16 hi = __float2bfloat16(v);
        __nv_bfloat16 lo = __float2bfloat16(v - __bfloat162float(hi));
        g_wuH[i2] = hi;
        g_wuL[i2] = lo;
        return;
    }
    int i3 = i2 - NW2;
    if (i3 < 2304 * 32) {
        int ck = i3 >> 5, oc = i3 & 31;
        g_woffT[i3] = (oc < 27) ? w_off[oc * 2304 + ck] : 0.f;
    }
}

// ---------------- dummy (ncu slot padding: capture = 4th launch, idx 3) ----------------
__global__ void dummy_kernel() {}

// ---------------- kernel 1: 3x3 offset conv (SIMT fma2) ------------
__global__ void __launch_bounds__(256, 2) conv_off_kernel(const float* __restrict__ x,
                                                          const float* __restrict__ b_off) {
    __shared__ float As[2][36][32];
    __shared__ float Bs[2][36][64];
    int b = blockIdx.x >> 6;
    int h = blockIdx.x & 63;
    int t = threadIdx.x;
    int ocp = t >> 4;
    int pb = (t & 15) << 2;
    const float* xb = x + b * 256 * 4096;
    ull acc[4];
#pragma unroll
    for (int j = 0; j < 4; j++) acc[j] = 0ull;
    float xv[9];

#define COFF_LOADB(c0)                                                          \
    {                                                                           \
        _Pragma("unroll")                                                       \
        for (int i = 0; i < 9; i++) {                                           \
            int e = t + (i << 8);                                               \
            int kc = e >> 6, wx = e & 63;                                       \
            int ci = kc / 9, kk = kc - ci * 9;                                  \
            int ky = kk / 3, kx = kk - ky * 3;                                  \
            int yy = h + ky - 1, xx = wx + kx - 1;                              \
            float v = 0.f;                                                      \
            if ((unsigned)yy < 64u && (unsigned)xx < 64u)                       \
                v = xb[((c0) + ci) * 4096 + yy * 64 + xx];                      \
            xv[i] = v;                                                          \
        }                                                                       \
    }
#define COFF_STOREB(dst)                                                        \
    {                                                                           \
        _Pragma("unroll")                                                       \
        for (int i = 0; i < 9; i++) {                                           \
            int e = t + (i << 8);                                               \
            int kc = e >> 6, wx = e & 63;                                       \
            Bs[dst][kc][wx] = xv[i];                                            \
        }                                                                       \
    }
#define COFF_LOADA(c0, dst)                                                     \
    {                                                                           \
        const float4* wsrc = (const float4*)(g_woffT + (c0) * 9 * 32);          \
        _Pragma("unroll")                                                       \
        for (int i = 0; i < 2; i++) {                                           \
            int e = t + (i << 8);                                               \
            if (e < 288) cp16(&((float4*)As[dst])[e], wsrc + e);                \
        }                                                                       \
        cp_commit();                                                            \
    }
#define COFF_COMPUTE(cc)                                                        \
    {                                                                           \
        _Pragma("unroll")                                                       \
        for (int kc = 0; kc < 36; kc++) {                                       \
            ull Au = *(const ull*)&As[cc][kc][ocp * 2];                         \
            float4 bv = *(const float4*)&Bs[cc][kc][pb];                        \
            fma2(acc[0], Au, dup2(bv.x));                                       \
            fma2(acc[1], Au, dup2(bv.y));                                       \
            fma2(acc[2], Au, dup2(bv.z));                                       \
            fma2(acc[3], Au, dup2(bv.w));                                       \
        }                                                                       \
    }

    int cur = 0;
    COFF_LOADA(0, 0)
    COFF_LOADB(0)
    COFF_STOREB(0)
    cp_wait0();
    __syncthreads();
    for (int c0 = 4; c0 < 256; c0 += 4) {
        int nxt = cur ^ 1;
        COFF_LOADA(c0, nxt)
        COFF_LOADB(c0)
        COFF_COMPUTE(cur)
        COFF_STOREB(nxt)
        cp_wait0();
        __syncthreads();
        cur = nxt;
    }
    COFF_COMPUTE(cur)

    int oc = 2 * ocp;
    if (oc < 27) {
        float2 p0 = unpk(acc[0]), p1 = unpk(acc[1]), p2 = unpk(acc[2]), p3 = unpk(acc[3]);
        float bo = b_off[oc];
        float4 lo = make_float4(p0.x + bo, p1.x + bo, p2.x + bo, p3.x + bo);
        *(float4*)&g_om[((b * 27 + oc) * 64 + h) * 64 + pb] = lo;
        if (oc + 1 < 27) {
            float b1 = b_off[oc + 1];
            float4 hi = make_float4(p0.y + b1, p1.y + b1, p2.y + b1, p3.y + b1);
            *(float4*)&g_om[((b * 27 + oc + 1) * 64 + h) * 64 + pb] = hi;
        }
    }
}

// ======== homogeneous MMA compute (8 warps, each 32x32 tile; chunk K=32) ========
// uses: sb, aoffBase, boffBase, acc[2][4][4]
#define MMA_COMPUTE(cc, AH, AL, BH, BL)                                         \
    {                                                                           \
        u32 aH = sb + AH[cc], aL = sb + AL[cc];                                 \
        u32 bH = sb + BH[cc], bL = sb + BL[cc];                                 \
        _Pragma("unroll")                                                       \
        for (int ks = 0; ks < 2; ks++) {                                        \
            u32 ka = (u32)ks * 32;                                              \
            u32 ah0[4], ah1[4], al0[4], al1[4];                                 \
            u32 bh0[4], bh1[4], bl0[4], bl1[4];                                 \
            ldsm4(ah0, aH + aoffBase + ka);                                     \
            ldsm4(ah1, aH + aoffBase + ka + 16 * PITCHB);                       \
            ldsm4(al0, aL + aoffBase + ka);                                     \
            ldsm4(al1, aL + aoffBase + ka + 16 * PITCHB);                       \
            ldsm4(bh0, bH + boffBase + ka);                                     \
            ldsm4(bh1, bH + boffBase + ka + 16 * PITCHB);                       \
            ldsm4(bl0, bL + boffBase + ka);                                     \
            ldsm4(bl1, bL + boffBase + ka + 16 * PITCHB);                       \
            mma16816(acc[0][0], ah0, bh0[0], bh0[1]);                           \
            mma16816(acc[0][1], ah0, bh0[2], bh0[3]);                           \
            mma16816(acc[0][2], ah0, bh1[0], bh1[1]);                           \
            mma16816(acc[0][3], ah0, bh1[2], bh1[3]);                           \
            mma16816(acc[1][0], ah1, bh0[0], bh0[1]);                           \
            mma16816(acc[1][1], ah1, bh0[2], bh0[3]);                           \
            mma16816(acc[1][2], ah1, bh1[0], bh1[1]);                           \
            mma16816(acc[1][3], ah1, bh1[2], bh1[3]);                           \
            mma16816(acc[0][0], ah0, bl0[0], bl0[1]);                           \
            mma16816(acc[0][1], ah0, bl0[2], bl0[3]);                           \
            mma16816(acc[0][2], ah0, bl1[0], bl1[1]);                           \
            mma16816(acc[0][3], ah0, bl1[2], bl1[3]);                           \
            mma16816(acc[1][0], ah1, bl0[0], bl0[1]);                           \
            mma16816(acc[1][1], ah1, bl0[2], bl0[3]);                           \
            mma16816(acc[1][2], ah1, bl1[0], bl1[1]);                           \
            mma16816(acc[1][3], ah1, bl1[2], bl1[3]);                           \
            mma16816(acc[0][0], al0, bh0[0], bh0[1]);                           \
            mma16816(acc[0][1], al0, bh0[2], bh0[3]);                           \
            mma16816(acc[0][2], al0, bh1[0], bh1[1]);                           \
            mma16816(acc[0][3], al0, bh1[2], bh1[3]);                           \
            mma16816(acc[1][0], al1, bh0[0], bh0[1]);                           \
            mma16816(acc[1][1], al1, bh0[2], bh0[3]);                           \
            mma16816(acc[1][2], al1, bh1[0], bh1[1]);                           \
            mma16816(acc[1][3], al1, bh1[2], bh1[3]);                           \
        }                                                                       \
    }

// ================= mdcn (chunk K=32, 2 CTA/SM) =================
#define MD_MW   0                   // metaW: 576*16 = 9216
#define MD_MI   9216                // metaI: 576*4 = 2304
#define MD_AH0  11520               // A tiles: 128 x 80B = 10240 each
#define MD_AH1  21760
#define MD_AL0  32000
#define MD_AL1  42240
#define MD_BH0  52480               // B tiles: 64 x 80B = 5120 each
#define MD_BH1  57600
#define MD_BL0  62720
#define MD_BL1  67840
#define MD_DS   MD_AH0              // epilogue 128x68 f32 = 34816 (fits 11520..46336)
#define MD_SMEM 72960

__global__ void __launch_bounds__(256, 2)
mdcn_mma_kernel(const float* __restrict__ x, const float* __restrict__ b_dcn) {
    extern __shared__ char sm[];
    u32 sb = smem_u32(sm);
    int b = blockIdx.x >> 6;
    int h = blockIdx.x & 63;
    int t = threadIdx.x;
    int wid = t >> 5;
    int lane = t & 31;

    float4* metaW = (float4*)(sm + MD_MW);
    u32* metaI = (u32*)(sm + MD_MI);

    for (int e = t; e < 576; e += 256) {
        int pixl = e / 9;
        int k = e - pixl * 9;
        int w = pixl;
        const float* omb = g_om + (b * 27) * 4096 + h * 64 + w;
        float dy = omb[(2 * k) * 4096];
        float dx = omb[(2 * k + 1) * 4096];
        float mr = omb[(18 + k) * 4096];
        float m = 1.f / (1.f + expf(-mr));
        int ky = k / 3, kx = k - ky * 3;
        float ys = (float)(h - 1 + ky) + dy;
        float xs = (float)(w - 1 + kx) + dx;
        float y0f = floorf(ys), x0f = floorf(xs);
        float ly = ys - y0f, lx = xs - x0f;
        int y0 = (int)y0f, x0 = (int)x0f;
        int y1 = y0 + 1, x1 = x0 + 1;
        float vy0 = ((unsigned)y0 < 64u) ? 1.f : 0.f;
        float vy1 = ((unsigned)y1 < 64u) ? 1.f : 0.f;
        float vx0 = ((unsigned)x0 < 64u) ? 1.f : 0.f;
        float vx1 = ((unsigned)x1 < 64u) ? 1.f : 0.f;
        int iy0 = min(max(y0, 0), 63), iy1 = min(max(y1, 0), 63);
        int ix0 = min(max(x0, 0), 63), ix1 = min(max(x1, 0), 63);
        float4 wv;
        wv.x = (1.f - ly) * (1.f - lx) * m * vy0 * vx0;
        wv.y = (1.f - ly) * lx * m * vy0 * vx1;
        wv.z = ly * (1.f - lx) * m * vy1 * vx0;
        wv.w = ly * lx * m * vy1 * vx1;
        metaW[e] = wv;
        metaI[e] = (u32)iy0 | ((u32)iy1 << 8) | ((u32)ix0 << 16) | ((u32)ix1 << 24);
    }
    __syncthreads();

    int m0 = (wid >> 1) * 32;
    int n0 = (wid & 1) * 32;
    float acc[2][4][4];
#pragma unroll
    for (int i = 0; i < 2; i++)
#pragma unroll
        for (int j = 0; j < 4; j++)
#pragma unroll
            for (int q = 0; q < 4; q++) acc[i][j][q] = 0.f;

    const float* xb = x + b * 256 * 4096;
    const int ahOff[2] = {MD_AH0, MD_AH1};
    const int alOff[2] = {MD_AL0, MD_AL1};
    const int bhOff[2] = {MD_BH0, MD_BH1};
    const int blOff[2] = {MD_BL0, MD_BL1};
    int px = t & 63;
    int kp0 = (t >> 6) * 2;       // pair base: 0/2/4/6

    u32 aoffBase = (u32)(m0 + (lane & 15)) * PITCHB + ((lane >> 4) << 4);
    u32 boffBase = (u32)(n0 + (lane & 7) + ((lane >> 4) << 3)) * PITCHB + (((lane >> 3) & 1) << 4);

#define MD_LOADA(c, dst)                                                        \
    {                                                                           \
        const char* srcH = (const char*)g_wAH + (c) * 8192;                     \
        const char* srcL = (const char*)g_wAL + (c) * 8192;                     \
        char* dH = sm + ahOff[dst];                                             \
        char* dL = sm + alOff[dst];                                             \
        _Pragma("unroll")                                                       \
        for (int i = 0; i < 2; i++) {                                           \
            int e = t + (i << 8);                                               \
            int oc = e >> 2, s = e & 3;                                         \
            cp16(dH + oc * PITCHB + s * 16, srcH + e * 16);                     \
            cp16(dL + oc * PITCHB + s * 16, srcL + e * 16);                     \
        }                                                                       \
        cp_commit();                                                            \
    }
#define MD_STOREB(c, dst)                                                       \
    {                                                                           \
        char* bh = sm + bhOff[dst];                                             \
        char* bl = sm + blOff[dst];                                             \
        _Pragma("unroll")                                                       \
        for (int j = 0; j < 4; j++) {                                           \
            int kin = kp0 + 8 * j;                                              \
            float v[2];                                                         \
            _Pragma("unroll")                                                   \
            for (int u = 0; u < 2; u++) {                                       \
                int k = (c) * 32 + kin + u;                                     \
                int ci = k / 9;                                                 \
                int kk = k - 9 * ci;                                            \
                int mi = px * 9 + kk;                                           \
                u32 pk = metaI[mi];                                             \
                float4 wv = metaW[mi];                                          \
                const float* xc = xb + (ci << 12);                              \
                int iy0 = pk & 255, iy1 = (pk >> 8) & 255;                      \
                int ix0 = (pk >> 16) & 255, ix1 = pk >> 24;                     \
                v[u] = wv.x * xc[iy0 * 64 + ix0] + wv.y * xc[iy0 * 64 + ix1]    \
                     + wv.z * xc[iy1 * 64 + ix0] + wv.w * xc[iy1 * 64 + ix1];   \
            }                                                                   \
            u32 u0 = __float_as_uint(v[0]), u1 = __float_as_uint(v[1]);         \
            u32 hp = (u0 >> 16) | (u1 & 0xFFFF0000u);                           \
            float l0 = v[0] - __uint_as_float(u0 & 0xFFFF0000u);                \
            float l1 = v[1] - __uint_as_float(u1 & 0xFFFF0000u);                \
            u32 lp = cvtpk(l0, l1);                                             \
            int off = px * PITCHB + kin * 2;                                    \
            *(u32*)(bh + off) = hp;                                             \
            *(u32*)(bl + off) = lp;                                             \
        }                                                                       \
    }

    int cur = 0;
    MD_LOADA(0, 0)
    MD_STOREB(0, 0)
    cp_wait0();
    __syncthreads();
    for (int c = 1; c < 72; c++) {
        int nxt = cur ^ 1;
        MD_LOADA(c, nxt)
        MMA_COMPUTE(cur, ahOff, alOff, bhOff, blOff)
        MD_STOREB(c, nxt)
        cp_wait0();
        __syncthreads();
        cur = nxt;
    }
    MMA_COMPUTE(cur, ahOff, alOff, bhOff, blOff)

    __syncthreads();
    float* Ds = (float*)(sm + MD_DS);
#pragma unroll
    for (int mt = 0; mt < 2; mt++)
#pragma unroll
        for (int nt = 0; nt < 4; nt++) {
            int m = m0 + mt * 16 + (lane >> 2);
            int n = n0 + nt * 8 + ((lane & 3) << 1);
            float* cp = acc[mt][nt];
            *(float2*)&Ds[m * 68 + n] = make_float2(cp[0], cp[1]);
            *(float2*)&Ds[(m + 8) * 68 + n] = make_float2(cp[2], cp[3]);
        }
    __syncthreads();
    {
        int oc8 = (t >> 4) * 8, w4 = (t & 15) * 4;
#pragma unroll
        for (int op = 0; op < 8; op++) {
            int oc = oc8 + op;
            float4 v = *(float4*)&Ds[oc * 68 + w4];
            float bb = b_dcn[oc];
            v.x += bb; v.y += bb; v.z += bb; v.w += bb;
            *(float4*)&g_y[((b * 128 + oc) << 12) + h * 64 + w4] = v;
        }
    }
}

// ---------------- BN stats ----------------
__global__ void __launch_bounds__(1024) bn_stats_kernel(const float* __restrict__ src, int shift,
                                                        const float* __restrict__ gamma,
                                                        const float* __restrict__ beta,
                                                        float* gs, float* gt) {
    int c = blockIdx.x;
    int t = threadIdx.x;
    float s = 0.f, q = 0.f;
    for (int i = t; i < (4 << (shift - 2)); i += 1024) {
        int bb = i >> (shift - 2);
        int r = i - (bb << (shift - 2));
        float4 v = ((const float4*)src)[(size_t)((bb * 128 + c) << (shift - 2)) + r];
        s += v.x + v.y + v.z + v.w;
        q += v.x * v.x + v.y * v.y + v.z * v.z + v.w * v.w;
    }
    __shared__ float rs[1024], rq[1024];
    rs[t] = s; rq[t] = q;
    __syncthreads();
    for (int o = 512; o > 0; o >>= 1) {
        if (t < o) { rs[t] += rs[t + o]; rq[t] += rq[t + o]; }
        __syncthreads();
    }
    if (t == 0) {
        float inv = 1.f / (float)(4 << shift);
        float mean = rs[0] * inv;
        float var = rq[0] * inv - mean * mean;
        float sc = gamma[c] * rsqrtf(var + 1e-5f);
        gs[c] = sc;
        gt[c] = beta[c] - mean * sc;
    }
}

// ================= deconv (chunk K=32, 2 CTA/SM) =================
#define DC_AH0  0
#define DC_AH1  10240
#define DC_AL0  20480
#define DC_AL1  30720
#define DC_BH0  40960
#define DC_BH1  46080
#define DC_BL0  51200
#define DC_BL1  56320
#define DC_BN   61440               // bn1 cache: 2 x 128 floats
#define DC_DS   0
#define DC_SMEM 62464

__global__ void __launch_bounds__(256, 2)
deconv_mma_kernel() {
    extern __shared__ char sm[];
    u32 sb = smem_u32(sm);
    int b = blockIdx.x >> 8;
    int rem = blockIdx.x & 255;
    int Y = rem >> 1;
    int pX = rem & 1;
    int p = ((Y & 1) << 1) | pX;
    int t = threadIdx.x;
    int wid = t >> 5;
    int lane = t & 31;

    float* bnS = (float*)(sm + DC_BN);
    float* bnT = (float*)(sm + DC_BN + 512);
    if (t < 128) { bnS[t] = g_bn1s[t]; bnT[t] = g_bn1t[t]; }
    __syncthreads();

    int m0 = (wid >> 1) * 32;
    int n0 = (wid & 1) * 32;
    float acc[2][4][4];
#pragma unroll
    for (int i = 0; i < 2; i++)
#pragma unroll
        for (int j = 0; j < 4; j++)
#pragma unroll
            for (int q = 0; q < 4; q++) acc[i][j][q] = 0.f;

    const float* yb = g_y + b * 128 * 4096;
    const int ahOff[2] = {DC_AH0, DC_AH1};
    const int alOff[2] = {DC_AL0, DC_AL1};
    const int bhOff[2] = {DC_BH0, DC_BH1};
    const int blOff[2] = {DC_BL0, DC_BL1};
    int px = t & 63;
    int kp0 = (t >> 6) * 2;

    u32 aoffBase = (u32)(m0 + (lane & 15)) * PITCHB + ((lane >> 4) << 4);
    u32 boffBase = (u32)(n0 + (lane & 7) + ((lane >> 4) << 3)) * PITCHB + (((lane >> 3) & 1) << 4);

#define DC_LOADA(c, dst)                                                        \
    {                                                                           \
        const char* srcH = (const char*)g_wuH + (p * 16 + (c)) * 8192;          \
        const char* srcL = (const char*)g_wuL + (p * 16 + (c)) * 8192;          \
        char* dH = sm + ahOff[dst];                                             \
        char* dL = sm + alOff[dst];                                             \
        _Pragma("unroll")                                                       \
        for (int i = 0; i < 2; i++) {                                           \
            int e = t + (i << 8);                                               \
            int oc = e >> 2, s = e & 3;                                         \
            cp16(dH + oc * PITCHB + s * 16, srcH + e * 16);                     \
            cp16(dL + oc * PITCHB + s * 16, srcL + e * 16);                     \
        }                                                                       \
        cp_commit();                                                            \
    }
#define DC_STOREB(c, dst)                                                       \
    {                                                                           \
        char* bh = sm + bhOff[dst];                                             \
        char* bl = sm + blOff[dst];                                             \
        _Pragma("unroll")                                                       \
        for (int j = 0; j < 4; j++) {                                           \
            int kin = kp0 + 8 * j;                                              \
            float v[2];                                                         \
            _Pragma("unroll")                                                   \
            for (int u = 0; u < 2; u++) {                                       \
                int k = (c) * 32 + kin + u;                                     \
                int cc2 = k >> 2;                                               \
                int tap = k & 3;                                                \
                int ky = ((Y & 1) ^ 1) + 2 * (tap >> 1);                        \
                int hh = (Y + 1 - ky) >> 1;                                     \
                int kx = (pX ^ 1) + 2 * (tap & 1);                              \
                int ww = px + ((pX + 1 - kx) >> 1);                             \
                float vv = 0.f;                                                 \
                if ((unsigned)hh < 64u && (unsigned)ww < 64u) {                 \
                    float yv = yb[(cc2 << 12) + hh * 64 + ww];                  \
                    vv = fmaxf(yv * bnS[cc2] + bnT[cc2], 0.f);                  \
                }                                                               \
                v[u] = vv;                                                      \
            }                                                                   \
            u32 u0 = __float_as_uint(v[0]), u1 = __float_as_uint(v[1]);         \
            u32 hp = (u0 >> 16) | (u1 & 0xFFFF0000u);                           \
            float l0 = v[0] - __uint_as_float(u0 & 0xFFFF0000u);                \
            float l1 = v[1] - __uint_as_float(u1 & 0xFFFF0000u);                \
            u32 lp = cvtpk(l0, l1);                                             \
            int off = px * PITCHB + kin * 2;                                    \
            *(u32*)(bh + off) = hp;                                             \
            *(u32*)(bl + off) = lp;                                             \
        }                                                                       \
    }

    int cur = 0;
    DC_LOADA(0, 0)
    DC_STOREB(0, 0)
    cp_wait0();
    __syncthreads();
    for (int c = 1; c < 16; c++) {
        int nxt = cur ^ 1;
        DC_LOADA(c, nxt)
        MMA_COMPUTE(cur, ahOff, alOff, bhOff, blOff)
        DC_STOREB(c, nxt)
        cp_wait0();
        __syncthreads();
        cur = nxt;
    }
    MMA_COMPUTE(cur, ahOff, alOff, bhOff, blOff)

    __syncthreads();
    float* Ds = (float*)(sm + DC_DS);
#pragma unroll
    for (int mt = 0; mt < 2; mt++)
#pragma unroll
        for (int nt = 0; nt < 4; nt++) {
            int m = m0 + mt * 16 + (lane >> 2);
            int n = n0 + nt * 8 + ((lane & 3) << 1);
            float* cp = acc[mt][nt];
            *(float2*)&Ds[m * 68 + n] = make_float2(cp[0], cp[1]);
            *(float2*)&Ds[(m + 8) * 68 + n] = make_float2(cp[2], cp[3]);
        }
    __syncthreads();
    {
        int oc8 = (t >> 4) * 8, w4 = (t & 15) * 4;
#pragma unroll
        for (int op = 0; op < 8; op++) {
            int oc = oc8 + op;
            float4 v = *(float4*)&Ds[oc * 68 + w4];
            size_t base = (size_t)((b * 128 + oc) * 128 + Y) * 128 + pX * 64 + w4;
            *(float4*)&g_up[base] = v;
        }
    }
}

// ---------------- BN2 + ReLU + parity de-interleave ----------------
__global__ void __launch_bounds__(256) final_kernel(float* __restrict__ out) {
    __shared__ float s[8][128];
    int row0 = blockIdx.x * 8;
    int r = threadIdx.x >> 5;
    int q = threadIdx.x & 31;
    int grow = row0 + r;
    ((float4*)s[r])[q] = ((const float4*)g_up)[grow * 32 + q];
    __syncthreads();
    int bo = grow >> 7;
    int oc = bo & 127;
    float sc = g_bn2s[oc], sh = g_bn2t[oc];
    float v0 = s[r][q * 2];
    float v1 = s[r][64 + q * 2];
    float v2 = s[r][q * 2 + 1];
    float v3 = s[r][64 + q * 2 + 1];
    float4 o4 = make_float4(fmaxf(v0 * sc + sh, 0.f), fmaxf(v1 * sc + sh, 0.f),
                            fmaxf(v2 * sc + sh, 0.f), fmaxf(v3 * sc + sh, 0.f));
    *(float4*)&out[grow * 128 + q * 4] = o4;
}

// ---------------- launch ----------------
extern "C" void kernel_launch(void* const* d_in, const int* in_sizes, int n_in,
                              void* d_out, int out_size) {
    const float* x      = (const float*)d_in[0];
    const float* w_off  = (const float*)d_in[1];
    const float* b_off  = (const float*)d_in[2];
    const float* w_dcn  = (const float*)d_in[3];
    const float* b_dcn  = (const float*)d_in[4];
    const float* gamma1 = (const float*)d_in[5];
    const float* beta1  = (const float*)d_in[6];
    const float* w_up   = (const float*)d_in[7];
    const float* gamma2 = (const float*)d_in[8];
    const float* beta2  = (const float*)d_in[9];

    (void)cudaFuncSetAttribute(mdcn_mma_kernel, cudaFuncAttributeMaxDynamicSharedMemorySize, MD_SMEM);
    (void)cudaFuncSetAttribute(deconv_mma_kernel, cudaFuncAttributeMaxDynamicSharedMemorySize, DC_SMEM);

    float* yptr;  cudaGetSymbolAddress((void**)&yptr, g_y);
    float* uptr;  cudaGetSymbolAddress((void**)&uptr, g_up);
    float* b1s;   cudaGetSymbolAddress((void**)&b1s, g_bn1s);
    float* b1t;   cudaGetSymbolAddress((void**)&b1t, g_bn1t);
    float* b2s;   cudaGetSymbolAddress((void**)&b2s, g_bn2s);
    float* b2t;   cudaGetSymbolAddress((void**)&b2t, g_bn2t);

    int prepN = 72 * 4096 + 4 * 16 * 4096 + 2304 * 32;
    prep_weights<<<(prepN + 255) / 256, 256>>>(w_off, w_dcn, w_up);   // idx 0
    conv_off_kernel<<<NB * 64, 256>>>(x, b_off);                      // idx 1
    dummy_kernel<<<1, 32>>>();                                        // idx 2
    mdcn_mma_kernel<<<NB * 64, 256, MD_SMEM>>>(x, b_dcn);             // idx 3 (ncu slot)
    bn_stats_kernel<<<128, 1024>>>(yptr, 12, gamma1, beta1, b1s, b1t);
    deconv_mma_kernel<<<NB * 256, 256, DC_SMEM>>>();
    bn_stats_kernel<<<128, 1024>>>(uptr, 14, gamma2, beta2, b2s, b2t);
    final_kernel<<<(NB * 128 * 128 * 128) / 1024, 256>>>((float*)d_out);
}